// round 9
// baseline (speedup 1.0000x reference)
#include <cuda_runtime.h>
#include <cuda_fp16.h>
#include <math.h>
#include <stdint.h>

#define B_ 8
#define N_ 2048
#define FIN 128
#define FOUT 64
#define NNODE (B_*N_)

// ---- gat tiling ----
#define BM2 64
#define BK2 32
#define NST2 (N_/BK2)       // 64 stages
#define PSTR2 40            // halfs per P row (80B stride: 16B-aligned, conflict-free)
#define PBUF2 (BM2*PSTR2)   // 2560 halfs
#define BSTR2 40
#define BNR 72              // 64 Wh cols + 8 ones/zeros rows
#define BBUF2 (BNR*BSTR2)   // 2880 halfs
// smem bytes: adj 4*64*32*4=32768 | P 2*2560*2=10240 | B 4*2880*2=23040 | Zs 256
#define OFFB_P   32768
#define OFFB_B   (32768+10240)
#define OFFB_Z   (OFFB_B+23040)
#define GAT_SMEM (OFFB_Z+256)        // 66304 B

// ---- prep smem (float units) ----
#define HSTR 132
#define WSTR 72
#define PREP_SMEM ((64*HSTR + 2*FIN*WSTR + 128 + 256)*4)   // 109056 B

// ---------------- scratch ----------------------------------------------------
__device__ __half g_WhT[(size_t)B_*FOUT*N_];    // [b][col][k] fp16
__device__ float g_f1[NNODE], g_f2[NNODE];
__device__ float g_E1p[NNODE], g_E1n[NNODE];    // row-rescaled
__device__ float g_E2p[NNODE], g_E2n[NNODE];

// ---------------- helpers ----------------------------------------------------
__device__ __forceinline__ uint32_t smem_u32(const void* p) {
    uint32_t a;
    asm("{ .reg .u64 t; cvta.to.shared.u64 t, %1; cvt.u32.u64 %0, t; }" : "=r"(a) : "l"(p));
    return a;
}
__device__ __forceinline__ float cvt_tf32(float x) {
    uint32_t u;
    asm("cvt.rna.tf32.f32 %0, %1;" : "=r"(u) : "f"(x));
    return __uint_as_float(u);
}
__device__ __forceinline__ void cp16(uint32_t dst, const void* src) {
    asm volatile("cp.async.cg.shared.global [%0], [%1], 16;" :: "r"(dst), "l"(src));
}
#define CP_COMMIT() asm volatile("cp.async.commit_group;" ::: "memory")
#define CP_WAIT2()  asm volatile("cp.async.wait_group 2;" ::: "memory")

#define MMA_TF32(D, A0, A1, A2, A3, Bb0, Bb1)                                   \
    asm("mma.sync.aligned.m16n8k8.row.col.f32.tf32.tf32.f32 "                   \
        "{%0,%1,%2,%3}, {%4,%5,%6,%7}, {%8,%9}, {%0,%1,%2,%3};"                 \
        : "+f"((D)[0]), "+f"((D)[1]), "+f"((D)[2]), "+f"((D)[3])                \
        : "r"(A0), "r"(A1), "r"(A2), "r"(A3), "r"(Bb0), "r"(Bb1))

#define MMA_F16(D, Aa, Bb0, Bb1)                                                \
    asm("mma.sync.aligned.m16n8k16.row.col.f32.f16.f16.f32 "                    \
        "{%0,%1,%2,%3}, {%4,%5,%6,%7}, {%8,%9}, {%0,%1,%2,%3};"                 \
        : "+f"((D)[0]), "+f"((D)[1]), "+f"((D)[2]), "+f"((D)[3])                \
        : "r"((Aa)[0]), "r"((Aa)[1]), "r"((Aa)[2]), "r"((Aa)[3]),               \
          "r"(Bb0), "r"(Bb1))

#define LDMATRIX_X4(Aa, addr)                                                   \
    asm volatile("ldmatrix.sync.aligned.m8n8.x4.shared.b16 {%0,%1,%2,%3}, [%4];"\
        : "=r"((Aa)[0]), "=r"((Aa)[1]), "=r"((Aa)[2]), "=r"((Aa)[3])            \
        : "r"(addr))

// ---------------------------------------------------------------------------
// Prep: 64-row CTAs. Wh = h@W via tf32 mma (A=h single tf32, B=W hi/lo split).
// Outputs: WhT fp16 [b][col][k] via smem transpose + coalesced STG; raw f1/f2.
// ---------------------------------------------------------------------------
__global__ void __launch_bounds__(256) prep_mma(const float* __restrict__ h,
                                                const float* __restrict__ W,
                                                const float* __restrict__ a) {
    extern __shared__ float sp_[];
    float* hs  = sp_;                        // [64][132]
    float* WsH = hs + 64*HSTR;               // [128][72]
    float* WsL = WsH + FIN*WSTR;             // [128][72]
    float* as_ = WsL + FIN*WSTR;             // [128]
    float* f1p = as_ + 128;                  // [2][64]
    float* f2p = f1p + 128;                  // [2][64]

    const int tid = threadIdx.x;
    const int i0 = blockIdx.x * 64;

    if (tid < 128) as_[tid] = a[tid];

#pragma unroll
    for (int it = 0; it < 8; it++) {
        const int lin = it*256 + tid;
        const int k = lin >> 4, c4 = (lin & 15) * 4;
        const float4 w = *(const float4*)(W + k*FOUT + c4);
        const float hx = cvt_tf32(w.x), hy = cvt_tf32(w.y);
        const float hz = cvt_tf32(w.z), hw = cvt_tf32(w.w);
        *(float4*)(WsH + k*WSTR + c4) = make_float4(hx, hy, hz, hw);
        *(float4*)(WsL + k*WSTR + c4) = make_float4(cvt_tf32(w.x-hx), cvt_tf32(w.y-hy),
                                                    cvt_tf32(w.z-hz), cvt_tf32(w.w-hw));
    }
#pragma unroll
    for (int it = 0; it < 8; it++) {
        const int lin = it*256 + tid;
        const int r = lin >> 5, c = (lin & 31) * 4;
        *(float4*)(hs + r*HSTR + c) = *(const float4*)(h + (size_t)(i0 + r)*FIN + c);
    }
    __syncthreads();

    const int wid = tid >> 5, lane = tid & 31;
    const int gid = lane >> 2, tig = lane & 3;
    const int mt4 = wid & 3;
    const int nh = wid >> 2;

    float acc[4][4] = {};
    const float* Ap = hs + (mt4*16 + gid)*HSTR + tig;
    const float* BH = WsH + tig*WSTR + nh*32 + gid;
    const float* BL = WsL + tig*WSTR + nh*32 + gid;

#pragma unroll
    for (int kq = 0; kq < 16; kq++) {
        const uint32_t A0 = __float_as_uint(cvt_tf32(Ap[kq*8]));
        const uint32_t A1 = __float_as_uint(cvt_tf32(Ap[kq*8 + 8*HSTR]));
        const uint32_t A2 = __float_as_uint(cvt_tf32(Ap[kq*8 + 4]));
        const uint32_t A3 = __float_as_uint(cvt_tf32(Ap[kq*8 + 4 + 8*HSTR]));
        const float* bh = BH + kq*8*WSTR;
        const float* bl = BL + kq*8*WSTR;
#pragma unroll
        for (int nt = 0; nt < 4; nt++) {
            const uint32_t bh0 = __float_as_uint(bh[nt*8]);
            const uint32_t bh1 = __float_as_uint(bh[nt*8 + 4*WSTR]);
            const uint32_t bl0 = __float_as_uint(bl[nt*8]);
            const uint32_t bl1 = __float_as_uint(bl[nt*8 + 4*WSTR]);
            MMA_TF32(acc[nt], A0, A1, A2, A3, bh0, bh1);
            MMA_TF32(acc[nt], A0, A1, A2, A3, bl0, bl1);
        }
    }

    float f1a = 0.f, f2a = 0.f, f1b = 0.f, f2b = 0.f;
#pragma unroll
    for (int nt = 0; nt < 4; nt++) {
        const int c = nh*32 + nt*8 + tig*2;
        const float a10 = as_[c], a11 = as_[c+1];
        const float a20 = as_[64+c], a21 = as_[64+c+1];
        f1a += acc[nt][0]*a10 + acc[nt][1]*a11;
        f2a += acc[nt][0]*a20 + acc[nt][1]*a21;
        f1b += acc[nt][2]*a10 + acc[nt][3]*a11;
        f2b += acc[nt][2]*a20 + acc[nt][3]*a21;
    }
#pragma unroll
    for (int o = 1; o <= 2; o <<= 1) {
        f1a += __shfl_xor_sync(0xffffffffu, f1a, o);
        f2a += __shfl_xor_sync(0xffffffffu, f2a, o);
        f1b += __shfl_xor_sync(0xffffffffu, f1b, o);
        f2b += __shfl_xor_sync(0xffffffffu, f2b, o);
    }
    if (tig == 0) {
        const int ri = mt4*16 + gid;
        f1p[nh*64 + ri] = f1a;   f1p[nh*64 + ri + 8] = f1b;
        f2p[nh*64 + ri] = f2a;   f2p[nh*64 + ri + 8] = f2b;
    }
    __syncthreads();

    __half* Wt = (__half*)sp_;
#pragma unroll
    for (int nt = 0; nt < 4; nt++) {
#pragma unroll
        for (int e = 0; e < 4; e++) {
            const int col = nh*32 + nt*8 + tig*2 + (e & 1);
            const int kl = mt4*16 + gid + ((e >> 1) << 3);
            Wt[col*72 + kl] = __float2half(acc[nt][e]);
        }
    }
    __syncthreads();

    const int bb = i0 >> 11;
    const int kbase = i0 & (N_-1);
    {
        const int col = tid >> 2, seg = tid & 3;
        const __half* srcw = Wt + col*72 + seg*16;
        __half* dstw = g_WhT + (size_t)bb*FOUT*N_ + (size_t)col*N_ + kbase + seg*16;
        *(uint4*)dstw = *(const uint4*)srcw;
        *(uint4*)(dstw + 8) = *(const uint4*)(srcw + 8);
    }
    if (tid < 64) {
        g_f1[i0 + tid] = f1p[tid] + f1p[64 + tid];
        g_f2[i0 + tid] = f2p[tid] + f2p[64 + tid];
    }
}

// ---------------------------------------------------------------------------
// Scalars: per batch, M2 = max_j f2; m_i = leakyrelu(f1_i + M2);
// row-rescale -> all P values <= 1 (fp16-safe); cancels in softmax.
// ---------------------------------------------------------------------------
__global__ void __launch_bounds__(256) scalars_kernel() {
    __shared__ float red[8];
    __shared__ float M2s;
    const int b = blockIdx.x, tid = threadIdx.x;
    const int base = b * N_;

    float m = -1e30f;
#pragma unroll
    for (int k = 0; k < 8; k++) m = fmaxf(m, g_f2[base + tid + k*256]);
#pragma unroll
    for (int o = 16; o > 0; o >>= 1) m = fmaxf(m, __shfl_xor_sync(0xffffffffu, m, o));
    if ((tid & 31) == 0) red[tid >> 5] = m;
    __syncthreads();
    if (tid == 0) {
        float mm = red[0];
#pragma unroll
        for (int i = 1; i < 8; i++) mm = fmaxf(mm, red[i]);
        M2s = mm;
    }
    __syncthreads();
    const float M2 = M2s;

#pragma unroll
    for (int k = 0; k < 8; k++) {
        const int node = base + tid + k*256;
        const float f1 = g_f1[node], f2 = g_f2[node];
        const float S = f1 + M2;
        const float mi = (S >= 0.f) ? S : 0.2f*S;
        g_E1p[node] = expf(f1 - mi);
        g_E1n[node] = expf(0.2f*f1 - mi);
        g_E2p[node] = expf(f2);
        g_E2n[node] = expf(0.2f*f2);
    }
}

// ---------------------------------------------------------------------------
// Main v2: CTA = (64 rows, batch); 64 stages of BK=32 over the FULL j range.
// 4-deep cp.async pipeline stages adj (int tiles) + B (WhT fp16) into smem;
// P built from smem adj; fp16 m16n8k16 mma; Z via ones row; out written
// directly (no combine pass, no partials).
// ---------------------------------------------------------------------------
__global__ void __launch_bounds__(256,3) gat_mma(const int* __restrict__ adj,
                                                 float* __restrict__ out) {
    extern __shared__ char smc[];
    const uint32_t sb = smem_u32(smc);
    int* adjS   = (int*)smc;                        // [4][64*32]
    __half* Pb  = (__half*)(smc + OFFB_P);          // [2][PBUF2]
    __half* Bb  = (__half*)(smc + OFFB_B);          // [4][BBUF2]
    float* Zs   = (float*)(smc + OFFB_Z);           // [64]

    const int tid = threadIdx.x;
    const int b  = blockIdx.y;
    const int i0 = blockIdx.x * BM2;
    const int nodeBase = b * N_;

    // ---- ones/zeros rows 64..71 of all 4 B buffers ----
    for (int idx = tid; idx < 4*8*BSTR2; idx += 256) {
        const int buf = idx / (8*BSTR2);
        const int rem = idx - buf*(8*BSTR2);
        const int rr = rem / BSTR2, cc = rem - rr*BSTR2;
        Bb[buf*BBUF2 + (64 + rr)*BSTR2 + cc] =
            (rr == 0 && cc < 32) ? __float2half(1.0f) : __float2half(0.0f);
    }

    // ---- staging maps ----
    const int ar = tid >> 2;                 // adj/B row 0..63
    const int a4o = (tid & 3) * 8;           // adj int offset (2x int4 chunks)
    const int bo  = (tid & 3) * 8;           // B half offset (16B)
    const int* adjSrc = adj + (size_t)b*N_*N_ + (size_t)(i0 + ar)*N_;
    const __half* bSrc = g_WhT + (size_t)b*FOUT*N_ + (size_t)ar*N_;

#define CPSTAGE(S) do {                                                          \
        const int _buf = (S) & 3;                                                \
        const uint32_t _ad = sb + (uint32_t)(_buf*2048 + ar*32 + a4o)*4;         \
        cp16(_ad,      adjSrc + (S)*BK2 + a4o);                                  \
        cp16(_ad + 16, adjSrc + (S)*BK2 + a4o + 4);                              \
        cp16(sb + OFFB_B + (uint32_t)(_buf*BBUF2 + ar*BSTR2 + bo)*2,             \
             bSrc + (S)*BK2 + bo);                                               \
        CP_COMMIT();                                                             \
    } while (0)

    // ---- P build map: 2 rows x 4 cols per thread ----
    const int rg2 = tid >> 3;                // 0..31 -> rows rg2*2..+1
    const int cg2 = tid & 7;                 // cols cg2*4..+3
    float e1pA, e1nA, e1pB, e1nB;
    {
        const int n0 = nodeBase + i0 + rg2*2;
        e1pA = g_E1p[n0];   e1nA = g_E1n[n0];
        e1pB = g_E1p[n0+1]; e1nB = g_E1n[n0+1];
    }

    // ---- GEMM map ----
    const int wid = tid >> 5, lane = tid & 31;
    const int gid = lane >> 2, tig = lane & 3;
    const int mt = wid & 3;                  // m16 tile
    const int nw = wid >> 2;                 // n-half
    const uint32_t abase = ((uint32_t)((mt*16 + (lane & 7) + ((lane >> 3) & 1)*8)*PSTR2
                            + (lane >> 4)*8)) * 2;

    float acc[4][4] = {};
    float accZ[4] = {};

    // ---- prologue: 3 stages in flight ----
    CPSTAGE(0); CPSTAGE(1); CPSTAGE(2);

    // scalars for stage 0
    float4 p2v = *(const float4*)(g_E2p + nodeBase + cg2*4);
    float4 n2v = *(const float4*)(g_E2n + nodeBase + cg2*4);

    for (int s = 0; s < NST2; s++) {
        CP_WAIT2();                 // stage s landed (<=2 groups pending)
        __syncthreads();            // visible to all; all warps done GEMM(s-1)

        if (s + 3 < NST2) CPSTAGE(s + 3);   // safe: buf (s-1)&3 free now

        // ---- P build from smem adj ----
        {
            const int* ap = adjS + (s & 3)*2048 + (rg2*2)*32 + cg2*4;
            const int4 av0 = *(const int4*)ap;
            const int4 av1 = *(const int4*)(ap + 32);
            const float p2a[4] = {p2v.x, p2v.y, p2v.z, p2v.w};
            const float n2a[4] = {n2v.x, n2v.y, n2v.z, n2v.w};
            float pA[4], pB[4];
            const int mA[4] = {av0.x, av0.y, av0.z, av0.w};
            const int mB[4] = {av1.x, av1.y, av1.z, av1.w};
#pragma unroll
            for (int c = 0; c < 4; c++) {
                const float vA = fmaxf(e1pA*p2a[c], e1nA*n2a[c]);
                const float vB = fmaxf(e1pB*p2a[c], e1nB*n2a[c]);
                pA[c] = (mA[c] != 0) ? vA : 0.f;
                pB[c] = (mB[c] != 0) ? vB : 0.f;
            }
            __half* Pw = Pb + (s & 1)*PBUF2;
            __half2 a01 = __floats2half2_rn(pA[0], pA[1]);
            __half2 a23 = __floats2half2_rn(pA[2], pA[3]);
            __half2 b01 = __floats2half2_rn(pB[0], pB[1]);
            __half2 b23 = __floats2half2_rn(pB[2], pB[3]);
            uint2 u0, u1;
            u0.x = *reinterpret_cast<uint32_t*>(&a01);
            u0.y = *reinterpret_cast<uint32_t*>(&a23);
            u1.x = *reinterpret_cast<uint32_t*>(&b01);
            u1.y = *reinterpret_cast<uint32_t*>(&b23);
            *(uint2*)(Pw + (rg2*2)*PSTR2 + cg2*4)     = u0;
            *(uint2*)(Pw + (rg2*2 + 1)*PSTR2 + cg2*4) = u1;
        }

        // prefetch scalars for stage s+1
        if (s + 1 < NST2) {
            const int cn = nodeBase + (s + 1)*BK2 + cg2*4;
            p2v = *(const float4*)(g_E2p + cn);
            n2v = *(const float4*)(g_E2n + cn);
        }

        __syncthreads();            // P(s) visible

        // ---- GEMM(s): 2 kq x (1 ldmatrix + 4 nt + ones) ----
        const uint32_t pPtr = sb + OFFB_P + (uint32_t)(s & 1)*PBUF2*2;
        const __half* Bs = Bb + (s & 3)*BBUF2;
#pragma unroll
        for (int kq = 0; kq < 2; kq++) {
            uint32_t A[4];
            LDMATRIX_X4(A, pPtr + abase + kq*32);
            const __half* Bk = Bs + kq*16 + tig*2;
#pragma unroll
            for (int nt = 0; nt < 4; nt++) {
                const int nrow = nw*32 + nt*8 + gid;
                const uint32_t b0 = *(const uint32_t*)(Bk + nrow*BSTR2);
                const uint32_t b1 = *(const uint32_t*)(Bk + nrow*BSTR2 + 8);
                MMA_F16(acc[nt], A, b0, b1);
            }
            if (nw == 1) {
                const uint32_t bo0 = *(const uint32_t*)(Bk + (64+gid)*BSTR2);
                const uint32_t bo1 = *(const uint32_t*)(Bk + (64+gid)*BSTR2 + 8);
                MMA_F16(accZ, A, bo0, bo1);
            }
        }
    }

    // ---- epilogue: Z exchange, divide, direct out store ----
    if (nw == 1 && tig == 0) {
        Zs[mt*16 + gid]     = accZ[0];
        Zs[mt*16 + gid + 8] = accZ[2];
    }
    __syncthreads();

    const int r0 = mt*16 + gid;
    const float inv0 = 1.0f / Zs[r0];
    const float inv1 = 1.0f / Zs[r0 + 8];
    float* outp = out + (size_t)(nodeBase + i0 + r0)*FOUT + nw*32 + tig*2;
#pragma unroll
    for (int nt = 0; nt < 4; nt++) {
        *(float2*)(outp + nt*8)            = make_float2(acc[nt][0]*inv0, acc[nt][1]*inv0);
        *(float2*)(outp + 8*FOUT + nt*8)   = make_float2(acc[nt][2]*inv1, acc[nt][3]*inv1);
    }
}

// ---------------------------------------------------------------------------
extern "C" void kernel_launch(void* const* d_in, const int* in_sizes, int n_in,
                              void* d_out, int out_size) {
    const float* h   = (const float*)d_in[0];
    const float* W   = (const float*)d_in[1];
    const float* a   = (const float*)d_in[2];
    const int*   adj = (const int*)d_in[3];
    float* out = (float*)d_out;

    cudaFuncSetAttribute(prep_mma, cudaFuncAttributeMaxDynamicSharedMemorySize, PREP_SMEM);
    prep_mma<<<NNODE/64, 256, PREP_SMEM>>>(h, W, a);

    scalars_kernel<<<B_, 256>>>();

    cudaFuncSetAttribute(gat_mma, cudaFuncAttributeMaxDynamicSharedMemorySize, GAT_SMEM);
    dim3 grid(N_/BM2, B_);
    gat_mma<<<grid, 256, GAT_SMEM>>>(adj, out);
}